// round 4
// baseline (speedup 1.0000x reference)
#include <cuda_runtime.h>

#define S       512
#define LOGS    9
#define BATCH   64
#define NCLUST  64
#define PNUM    (S*S)
#define TILE    16
#define TSTRIDE 17   // padded to kill smem bank conflicts in column tiles

// ---------------- scratch (no allocation allowed) ----------------
__device__ float2 d_spec[(size_t)BATCH * S * S];   // 128 MB spectrum workspace
__device__ int    d_winner[S * S];
__device__ int    d_cid[S * S];                    // cid per (m,k) in bit-reversed+shifted storage order
__device__ float2 d_tw[S / 2];                     // exp(-2*pi*i*k/S), k<256

__device__ __forceinline__ int brev9(int x) { return (int)(__brev((unsigned)x) >> 23); }

__device__ __forceinline__ float2 cadd(float2 a, float2 b) { return make_float2(a.x + b.x, a.y + b.y); }
__device__ __forceinline__ float2 csub(float2 a, float2 b) { return make_float2(a.x - b.x, a.y - b.y); }
__device__ __forceinline__ float2 cmul(float2 a, float2 w) {           // a * w
    return make_float2(a.x * w.x - a.y * w.y, a.x * w.y + a.y * w.x);
}
__device__ __forceinline__ float2 cmulc(float2 a, float2 w) {          // a * conj(w)
    return make_float2(a.x * w.x + a.y * w.y, a.y * w.x - a.x * w.y);
}

// ---------------- setup kernels ----------------
__global__ void k_init() {
    int t = blockIdx.x * blockDim.x + threadIdx.x;
    if (t < S / 2) {
        float sp, cp;
        sincospif((float)t / (float)(S / 2), &sp, &cp);   // theta = pi*t/256 = 2*pi*t/512
        d_tw[t] = make_float2(cp, -sp);
    }
    for (int i = t; i < S * S; i += gridDim.x * blockDim.x)
        d_winner[i] = -1;
}

// Scatter: last update (largest p) wins per cell, matching in-order scatter semantics.
// Cell coords fold in ifftshift (+S/2) AND bit-reversal (storage order of our DIF outputs).
__global__ void k_scatter(const int* __restrict__ idxx, const int* __restrict__ idxy) {
    int p = blockIdx.x * blockDim.x + threadIdx.x;
    if (p >= PNUM) return;
    int u = (idxx[p] + S / 2) & (S - 1);
    int v = (idxy[p] + S / 2) & (S - 1);
    atomicMax(&d_winner[brev9(u) * S + brev9(v)], p);
}

__global__ void k_cid(const int* __restrict__ cluster_id) {
    int i = blockIdx.x * blockDim.x + threadIdx.x;
    if (i >= S * S) return;
    int w = d_winner[i];
    d_cid[i] = (w >= 0) ? cluster_id[w] : -1;
}

// ---------------- pass 1: forward DIF along axis i (columns), real input ----------------
// grid (S/TILE, BATCH), 256 threads, dynamic smem = S*TSTRIDE*sizeof(float2)
__global__ void k_cols_fwd(const float* __restrict__ x) {
    extern __shared__ float2 sm[];
    int b = blockIdx.y;
    int k0 = blockIdx.x * TILE;
    int t = threadIdx.x;
    int c = t & (TILE - 1);
    int q = t >> 4;

    const float* xp = x + (size_t)b * S * S + k0 + c;
#pragma unroll
    for (int r = 0; r < S / TILE; r++) {
        int i = q + (r << 4);
        sm[i * TSTRIDE + c] = make_float2(xp[(size_t)i * S], 0.f);
    }
    __syncthreads();

#pragma unroll
    for (int s = 0; s < LOGS; s++) {
        int len  = (S / 2) >> s;
        int mult = 1 << s;
#pragma unroll
        for (int r = 0; r < 16; r++) {
            int bb = q + (r << 4);
            int j  = bb & (len - 1);
            int i0 = 2 * bb - j;
            float2 a  = sm[i0 * TSTRIDE + c];
            float2 cc = sm[(i0 + len) * TSTRIDE + c];
            float2 w  = d_tw[j * mult];
            sm[i0 * TSTRIDE + c]        = cadd(a, cc);
            sm[(i0 + len) * TSTRIDE + c] = cmul(csub(a, cc), w);
        }
        __syncthreads();
    }

    float2* sp = d_spec + (size_t)b * S * S + k0 + c;
#pragma unroll
    for (int r = 0; r < S / TILE; r++) {
        int i = q + (r << 4);
        sp[(size_t)i * S] = sm[i * TSTRIDE + c];
    }
}

// ---------------- pass 2: fused row DIF + mask*(1/S^2) + row DIT inverse ----------------
// grid (S, BATCH), 256 threads
__global__ void k_rows_fmi(const float* __restrict__ pi) {
    __shared__ float2 sm[S];
    int b = blockIdx.y;
    int m = blockIdx.x;
    int t = threadIdx.x;

    float2* row = d_spec + ((size_t)(b * S + m)) * S;
    sm[t]       = row[t];
    sm[t + 256] = row[t + 256];
    __syncthreads();

    // forward DIF along j
#pragma unroll
    for (int s = 0; s < LOGS; s++) {
        int len  = (S / 2) >> s;
        int mult = 1 << s;
        int j  = t & (len - 1);
        int i0 = 2 * t - j;
        float2 a  = sm[i0];
        float2 cc = sm[i0 + len];
        float2 w  = d_tw[j * mult];
        sm[i0]       = cadd(a, cc);
        sm[i0 + len] = cmul(csub(a, cc), w);
        __syncthreads();
    }

    // mask multiply (cid table already in storage order) + 1/S^2 normalization
    {
        const int* cr = d_cid + m * S;
        const float invN2 = 1.f / (float)(S * S);
        int c0 = cr[t], c1 = cr[t + 256];
        float f0 = ((c0 >= 0) ? pi[b * NCLUST + c0] : 1.f) * invN2;
        float f1 = ((c1 >= 0) ? pi[b * NCLUST + c1] : 1.f) * invN2;
        sm[t].x       *= f0; sm[t].y       *= f0;
        sm[t + 256].x *= f1; sm[t + 256].y *= f1;
    }
    __syncthreads();

    // inverse DIT along j (bit-reversed in -> natural out)
#pragma unroll
    for (int s = 0; s < LOGS; s++) {
        int len  = 1 << s;
        int mult = 256 >> s;
        int j  = t & (len - 1);
        int i0 = 2 * t - j;
        float2 a  = sm[i0];
        float2 w  = d_tw[j * mult];
        float2 cc = cmulc(sm[i0 + len], w);
        sm[i0]       = cadd(a, cc);
        sm[i0 + len] = csub(a, cc);
        __syncthreads();
    }

    row[t]       = sm[t];
    row[t + 256] = sm[t + 256];
}

// ---------------- pass 3: inverse DIT along axis i, write real part ----------------
__global__ void k_cols_inv(float* __restrict__ out) {
    extern __shared__ float2 sm[];
    int b = blockIdx.y;
    int k0 = blockIdx.x * TILE;
    int t = threadIdx.x;
    int c = t & (TILE - 1);
    int q = t >> 4;

    float2* sp = d_spec + (size_t)b * S * S + k0 + c;
#pragma unroll
    for (int r = 0; r < S / TILE; r++) {
        int i = q + (r << 4);
        sm[i * TSTRIDE + c] = sp[(size_t)i * S];
    }
    __syncthreads();

#pragma unroll
    for (int s = 0; s < LOGS; s++) {
        int len  = 1 << s;
        int mult = 256 >> s;
#pragma unroll
        for (int r = 0; r < 16; r++) {
            int bb = q + (r << 4);
            int j  = bb & (len - 1);
            int i0 = 2 * bb - j;
            float2 a  = sm[i0 * TSTRIDE + c];
            float2 w  = d_tw[j * mult];
            float2 cc = cmulc(sm[(i0 + len) * TSTRIDE + c], w);
            sm[i0 * TSTRIDE + c]         = cadd(a, cc);
            sm[(i0 + len) * TSTRIDE + c] = csub(a, cc);
        }
        __syncthreads();
    }

    float* op = out + (size_t)b * S * S + k0 + c;
#pragma unroll
    for (int r = 0; r < S / TILE; r++) {
        int i = q + (r << 4);
        op[(size_t)i * S] = sm[i * TSTRIDE + c].x;
    }
}

// ---------------- launch ----------------
extern "C" void kernel_launch(void* const* d_in, const int* in_sizes, int n_in,
                              void* d_out, int out_size) {
    const float* x    = (const float*)d_in[0];
    const float* pi   = (const float*)d_in[1];
    const int*   idxx = (const int*)d_in[2];
    const int*   idxy = (const int*)d_in[3];
    const int*   cid  = (const int*)d_in[4];
    float* out = (float*)d_out;

    const int smemTile = S * TSTRIDE * sizeof(float2);   // 69632 B
    cudaFuncSetAttribute(k_cols_fwd, cudaFuncAttributeMaxDynamicSharedMemorySize, smemTile);
    cudaFuncSetAttribute(k_cols_inv, cudaFuncAttributeMaxDynamicSharedMemorySize, smemTile);

    k_init<<<256, 1024>>>();
    k_scatter<<<PNUM / 256, 256>>>(idxx, idxy);
    k_cid<<<PNUM / 256, 256>>>(cid);

    dim3 gTile(S / TILE, BATCH);
    k_cols_fwd<<<gTile, 256, smemTile>>>(x);
    k_rows_fmi<<<dim3(S, BATCH), 256>>>(pi);
    k_cols_inv<<<gTile, 256, smemTile>>>(out);
}

// round 7
// speedup vs baseline: 2.5807x; 2.5807x over previous
#include <cuda_runtime.h>

#define S       512
#define LOGS    9
#define BATCH   64
#define NPAIR   (BATCH/2)
#define NCLUST  64
#define PNUM    (S*S)
#define TILE    16
#define TSTRIDE 17   // padded stride for column tiles

// ---------------- scratch (no allocation allowed) ----------------
__device__ float2 d_spec[(size_t)NPAIR * S * S];   // 64 MB packed-pair spectrum
__device__ int    d_winner[S * S];
__device__ int    d_cid[S * S];                    // cid per cell, bit-reversed+shifted storage order
__device__ float2 d_tw[S / 2];                     // exp(-2*pi*i*k/S)

__device__ __forceinline__ int brev9(int x) { return (int)(__brev((unsigned)x) >> 23); }

__device__ __forceinline__ float2 cadd(float2 a, float2 b) { return make_float2(a.x + b.x, a.y + b.y); }
__device__ __forceinline__ float2 csub(float2 a, float2 b) { return make_float2(a.x - b.x, a.y - b.y); }
__device__ __forceinline__ float2 cmul(float2 a, float2 w) {
    return make_float2(a.x * w.x - a.y * w.y, a.x * w.y + a.y * w.x);
}
__device__ __forceinline__ float2 cmulc(float2 a, float2 w) {          // a * conj(w)
    return make_float2(a.x * w.x + a.y * w.y, a.y * w.x - a.x * w.y);
}

// Fused radix-4 = two radix-2 DIF stages (first stage length L, twiddle step mult).
// Quad {g, g+L/2, g+L, g+3L/2}; identical layout/permutation as two radix-2 stages.
template<int STRIDE>
__device__ __forceinline__ void dif_quad(float2* p, int g, int L, int mult) {
    const int h  = L >> 1;
    const int j1 = g & (2 * L - 1);          // < h by quad construction
    float2 a = p[g * STRIDE];
    float2 b = p[(g + h) * STRIDE];
    float2 c = p[(g + L) * STRIDE];
    float2 d = p[(g + 3 * h) * STRIDE];
    float2 w1 = d_tw[j1 * mult];
    float2 w2 = d_tw[(j1 + h) * mult];
    float2 a1 = cadd(a, c);
    float2 c1 = cmul(csub(a, c), w1);
    float2 b1 = cadd(b, d);
    float2 d1 = cmul(csub(b, d), w2);
    float2 w3 = d_tw[j1 * (2 * mult)];
    p[g * STRIDE]           = cadd(a1, b1);
    p[(g + h) * STRIDE]     = cmul(csub(a1, b1), w3);
    p[(g + L) * STRIDE]     = cadd(c1, d1);
    p[(g + 3 * h) * STRIDE] = cmul(csub(c1, d1), w3);
}

// Fused two radix-2 DIT stages (first stage length l, twiddle step mult = 256>>s).
// Quad {g, g+l, g+2l, g+3l}.
template<int STRIDE>
__device__ __forceinline__ void dit_quad(float2* p, int g, int l, int mult) {
    const int j0 = g & (4 * l - 1);          // < l by quad construction
    float2 a = p[g * STRIDE];
    float2 b = p[(g + l) * STRIDE];
    float2 c = p[(g + 2 * l) * STRIDE];
    float2 d = p[(g + 3 * l) * STRIDE];
    float2 w  = d_tw[j0 * mult];
    float2 t1 = cmulc(b, w);
    float2 t2 = cmulc(d, w);
    float2 a1 = cadd(a, t1), b1 = csub(a, t1);
    float2 c1 = cadd(c, t2), d1 = csub(c, t2);
    const int m2 = mult >> 1;
    float2 u1 = cmulc(c1, d_tw[j0 * m2]);
    float2 u2 = cmulc(d1, d_tw[(j0 + l) * m2]);
    p[g * STRIDE]           = cadd(a1, u1);
    p[(g + 2 * l) * STRIDE] = csub(a1, u1);
    p[(g + l) * STRIDE]     = cadd(b1, u2);
    p[(g + 3 * l) * STRIDE] = csub(b1, u2);
}

// ---------------- setup kernels ----------------
__global__ void k_init() {
    int t = blockIdx.x * blockDim.x + threadIdx.x;
    if (t < S / 2) {
        float sp, cp;
        sincospif((float)t / (float)(S / 2), &sp, &cp);
        d_tw[t] = make_float2(cp, -sp);
    }
    for (int i = t; i < S * S; i += gridDim.x * blockDim.x)
        d_winner[i] = -1;
}

__global__ void k_scatter(const int* __restrict__ idxx, const int* __restrict__ idxy) {
    int p = blockIdx.x * blockDim.x + threadIdx.x;
    if (p >= PNUM) return;
    int u = (idxx[p] + S / 2) & (S - 1);
    int v = (idxy[p] + S / 2) & (S - 1);
    atomicMax(&d_winner[brev9(u) * S + brev9(v)], p);
}

__global__ void k_cid(const int* __restrict__ cluster_id) {
    int i = blockIdx.x * blockDim.x + threadIdx.x;
    if (i >= S * S) return;
    int w = d_winner[i];
    d_cid[i] = (w >= 0) ? cluster_id[w] : -1;
}

// ---------------- pass 1: forward DIF along columns, batch-pair packed ----------------
// grid (S/TILE, NPAIR), 256 threads, dyn smem = S*TSTRIDE*8
__global__ void k_cols_fwd(const float* __restrict__ x) {
    extern __shared__ float2 sm[];
    int pair = blockIdx.y;
    int k0 = blockIdx.x * TILE;
    int t = threadIdx.x;
    int c = t & (TILE - 1);
    int q = t >> 4;

    const float* x0 = x + (size_t)(2 * pair) * S * S + k0 + c;
    const float* x1 = x0 + (size_t)S * S;
#pragma unroll
    for (int r = 0; r < S / TILE; r++) {
        int i = q + (r << 4);
        sm[i * TSTRIDE + c] = make_float2(x0[(size_t)i * S], x1[(size_t)i * S]);
    }
    __syncthreads();

    float2* p = sm + c;
#pragma unroll
    for (int sp = 0; sp < 4; sp++) {
        const int L = 256 >> (2 * sp);
        const int mult = 1 << (2 * sp);
        const int h = L >> 1;
#pragma unroll
        for (int u = 0; u < 8; u++) {
            int qid = q + (u << 4);
            int g = (qid / h) * (2 * L) + (qid & (h - 1));
            dif_quad<TSTRIDE>(p, g, L, mult);
        }
        __syncthreads();
    }
    // standalone final stage (len=1, w=1)
#pragma unroll
    for (int u = 0; u < 16; u++) {
        int i0 = 2 * (q + (u << 4));
        float2 a = p[i0 * TSTRIDE], cc = p[(i0 + 1) * TSTRIDE];
        p[i0 * TSTRIDE] = cadd(a, cc);
        p[(i0 + 1) * TSTRIDE] = csub(a, cc);
    }
    __syncthreads();

    float2* spp = d_spec + (size_t)pair * S * S + k0 + c;
#pragma unroll
    for (int r = 0; r < S / TILE; r++) {
        int i = q + (r << 4);
        spp[(size_t)i * S] = sm[i * TSTRIDE + c];
    }
}

// ---------------- pass 2: row pair fwd FFT + Hermitian mask combine + inverse ----------------
// grid (S/2, NPAIR), 256 threads. Block bu pairs true-freq rows (u, S-u); bu==0 handles
// the two self-conjugate rows u=0 (storage 0) and u=256 (storage 1).
__global__ void k_rows_fmi(const float* __restrict__ pi) {
    __shared__ float2 Z[2][S];
    __shared__ float2 Y[2][S];
    int pair = blockIdx.y;
    int bu = blockIdx.x;
    int t = threadIdx.x;

    int rA, rB, selfp;
    if (bu == 0) { rA = 0; rB = 1; selfp = 1; }
    else         { rA = brev9(bu); rB = brev9(S - bu); selfp = 0; }

    float2* rowA = d_spec + ((size_t)pair * S + rA) * S;
    float2* rowB = d_spec + ((size_t)pair * S + rB) * S;
    Z[0][t] = rowA[t]; Z[0][t + 256] = rowA[t + 256];
    Z[1][t] = rowB[t]; Z[1][t + 256] = rowB[t + 256];
    __syncthreads();

    int r = t >> 7;
    int qid = t & 127;

    // forward DIF, both rows
#pragma unroll
    for (int sp = 0; sp < 4; sp++) {
        const int L = 256 >> (2 * sp);
        const int mult = 1 << (2 * sp);
        const int h = L >> 1;
        int g = (qid / h) * (2 * L) + (qid & (h - 1));
        dif_quad<1>(Z[r], g, L, mult);
        __syncthreads();
    }
#pragma unroll
    for (int u = 0; u < 2; u++) {
        int i0 = 2 * (qid + (u << 7));
        float2 a = Z[r][i0], cc = Z[r][i0 + 1];
        Z[r][i0] = cadd(a, cc);
        Z[r][i0 + 1] = csub(a, cc);
    }
    __syncthreads();

    // Hermitian mask combine: Q(k) = alpha*Z(k) + beta*conj(Z(-k))
    {
        const float invq = 0.25f / (float)(S * S);
        const float* pi0 = pi + (2 * pair) * NCLUST;
        const float* pi1 = pi0 + NCLUST;
#pragma unroll
        for (int rr = 0; rr < 2; rr++) {
            int rs = rr ? rB : rA;                 // this row's storage index
            int ps = selfp ? rs : (rr ? rA : rB);  // partner row's storage index
            int prr = selfp ? rr : (1 - rr);       // partner row's smem slot
#pragma unroll
            for (int kk = 0; kk < 2; kk++) {
                int k = t + (kk << 8);
                int kt = brev9((S - brev9(k)) & (S - 1));   // storage col of -v
                int c0 = d_cid[rs * S + k];
                int c1 = d_cid[ps * S + kt];
                float m0k = (c0 >= 0) ? pi0[c0] : 1.f;
                float m1k = (c0 >= 0) ? pi1[c0] : 1.f;
                float m0p = (c1 >= 0) ? pi0[c1] : 1.f;
                float m1p = (c1 >= 0) ? pi1[c1] : 1.f;
                float alpha = (m0k + m0p + m1k + m1p) * invq;
                float beta  = (m0k + m0p - m1k - m1p) * invq;
                float2 zk = Z[rr][k];
                float2 zp = Z[prr][kt];
                Y[rr][k] = make_float2(alpha * zk.x + beta * zp.x,
                                       alpha * zk.y - beta * zp.y);
            }
        }
    }
    __syncthreads();

    // inverse DIT, both rows
#pragma unroll
    for (int sp = 0; sp < 4; sp++) {
        const int l = 1 << (2 * sp);
        const int mult = 256 >> (2 * sp);
        int g = (qid / l) * (4 * l) + (qid & (l - 1));
        dit_quad<1>(Y[r], g, l, mult);
        __syncthreads();
    }
#pragma unroll
    for (int u = 0; u < 2; u++) {
        int bb = qid + (u << 7);
        float2 a = Y[r][bb];
        float2 cc = cmulc(Y[r][bb + 256], d_tw[bb]);
        Y[r][bb] = cadd(a, cc);
        Y[r][bb + 256] = csub(a, cc);
    }
    __syncthreads();

    rowA[t] = Y[0][t]; rowA[t + 256] = Y[0][t + 256];
    rowB[t] = Y[1][t]; rowB[t + 256] = Y[1][t + 256];
}

// ---------------- pass 3: inverse DIT along columns, unpack pair to two real batches ----------------
__global__ void k_cols_inv(float* __restrict__ out) {
    extern __shared__ float2 sm[];
    int pair = blockIdx.y;
    int k0 = blockIdx.x * TILE;
    int t = threadIdx.x;
    int c = t & (TILE - 1);
    int q = t >> 4;

    float2* spp = d_spec + (size_t)pair * S * S + k0 + c;
#pragma unroll
    for (int r = 0; r < S / TILE; r++) {
        int i = q + (r << 4);
        sm[i * TSTRIDE + c] = spp[(size_t)i * S];
    }
    __syncthreads();

    float2* p = sm + c;
#pragma unroll
    for (int sp = 0; sp < 4; sp++) {
        const int l = 1 << (2 * sp);
        const int mult = 256 >> (2 * sp);
#pragma unroll
        for (int u = 0; u < 8; u++) {
            int qid = q + (u << 4);
            int g = (qid / l) * (4 * l) + (qid & (l - 1));
            dit_quad<TSTRIDE>(p, g, l, mult);
        }
        __syncthreads();
    }
    // standalone final stage (len=256)
#pragma unroll
    for (int u = 0; u < 16; u++) {
        int bb = q + (u << 4);
        float2 a = p[bb * TSTRIDE];
        float2 cc = cmulc(p[(bb + 256) * TSTRIDE], d_tw[bb]);
        p[bb * TSTRIDE] = cadd(a, cc);
        p[(bb + 256) * TSTRIDE] = csub(a, cc);
    }
    __syncthreads();

    float* o0 = out + (size_t)(2 * pair) * S * S + k0 + c;
    float* o1 = o0 + (size_t)S * S;
#pragma unroll
    for (int r = 0; r < S / TILE; r++) {
        int i = q + (r << 4);
        float2 v = sm[i * TSTRIDE + c];
        o0[(size_t)i * S] = v.x;
        o1[(size_t)i * S] = v.y;
    }
}

// ---------------- launch ----------------
extern "C" void kernel_launch(void* const* d_in, const int* in_sizes, int n_in,
                              void* d_out, int out_size) {
    const float* x    = (const float*)d_in[0];
    const float* pi   = (const float*)d_in[1];
    const int*   idxx = (const int*)d_in[2];
    const int*   idxy = (const int*)d_in[3];
    const int*   cid  = (const int*)d_in[4];
    float* out = (float*)d_out;

    const int smemTile = S * TSTRIDE * sizeof(float2);   // 69632 B
    cudaFuncSetAttribute(k_cols_fwd, cudaFuncAttributeMaxDynamicSharedMemorySize, smemTile);
    cudaFuncSetAttribute(k_cols_inv, cudaFuncAttributeMaxDynamicSharedMemorySize, smemTile);

    k_init<<<256, 1024>>>();
    k_scatter<<<PNUM / 256, 256>>>(idxx, idxy);
    k_cid<<<PNUM / 256, 256>>>(cid);

    dim3 gTile(S / TILE, NPAIR);
    k_cols_fwd<<<gTile, 256, smemTile>>>(x);
    k_rows_fmi<<<dim3(S / 2, NPAIR), 256>>>(pi);
    k_cols_inv<<<gTile, 256, smemTile>>>(out);
}

// round 9
// speedup vs baseline: 3.0337x; 1.1755x over previous
#include <cuda_runtime.h>

#define S       512
#define BATCH   64
#define NPAIR   (BATCH/2)
#define NCLUST  64
#define PNUM    (S*S)

// ---------------- scratch ----------------
__device__ float2 d_spec[(size_t)NPAIR * S * S];   // 64 MB packed-pair spectrum
__device__ int    d_winner[S * S];
__device__ int2   d_cidp[S * S];                   // permuted (own, partner) cid table
__device__ float2 d_tw[S / 2];                     // exp(-2*pi*i*k/512)

__device__ __forceinline__ int brev9(int x) { return (int)(__brev((unsigned)x) >> 23); }

__device__ __forceinline__ float2 cadd(float2 a, float2 b) { return make_float2(a.x + b.x, a.y + b.y); }
__device__ __forceinline__ float2 csub(float2 a, float2 b) { return make_float2(a.x - b.x, a.y - b.y); }
__device__ __forceinline__ float2 cmul(float2 a, float2 w) {
    return make_float2(a.x * w.x - a.y * w.y, a.x * w.y + a.y * w.x);
}
__device__ __forceinline__ float2 cmulc(float2 a, float2 w) {          // a * conj(w)
    return make_float2(a.x * w.x + a.y * w.y, a.y * w.x - a.x * w.y);
}

// ---------------- fully-unrolled 16-point FFTs (literal twiddles) ----------------
#define C1f 0.92387953251128674f
#define S1f 0.38268343236508978f
#define R2f 0.70710678118654752f

#define DIF_BF(a,b,wr,wi) { float2 _d = csub(a,b); a = cadd(a,b); \
    b = make_float2(_d.x*(wr)-_d.y*(wi), _d.x*(wi)+_d.y*(wr)); }
#define DIF_BF1(a,b)  { float2 _d = csub(a,b); a = cadd(a,b); b = _d; }
#define DIF_BFmi(a,b) { float2 _d = csub(a,b); a = cadd(a,b); b = make_float2(_d.y, -_d.x); }

#define DIT_BF(a,b,wr,wi) { float2 _c = make_float2(b.x*(wr)-b.y*(wi), b.x*(wi)+b.y*(wr)); \
    b = csub(a,_c); a = cadd(a,_c); }
#define DIT_BF1(a,b)  { float2 _c = b; b = csub(a,_c); a = cadd(a,_c); }
#define DIT_BFpi(a,b) { float2 _c = make_float2(-b.y, b.x); b = csub(a,_c); a = cadd(a,_c); }

__device__ __forceinline__ void fft16_dif(float2* r) {
    DIF_BF1(r[0],r[8]);
    DIF_BF (r[1],r[9],  C1f,-S1f);
    DIF_BF (r[2],r[10], R2f,-R2f);
    DIF_BF (r[3],r[11], S1f,-C1f);
    DIF_BFmi(r[4],r[12]);
    DIF_BF (r[5],r[13],-S1f,-C1f);
    DIF_BF (r[6],r[14],-R2f,-R2f);
    DIF_BF (r[7],r[15],-C1f,-S1f);

    DIF_BF1(r[0],r[4]);  DIF_BF(r[1],r[5],R2f,-R2f);  DIF_BFmi(r[2],r[6]);  DIF_BF(r[3],r[7],-R2f,-R2f);
    DIF_BF1(r[8],r[12]); DIF_BF(r[9],r[13],R2f,-R2f); DIF_BFmi(r[10],r[14]); DIF_BF(r[11],r[15],-R2f,-R2f);

    DIF_BF1(r[0],r[2]);   DIF_BFmi(r[1],r[3]);
    DIF_BF1(r[4],r[6]);   DIF_BFmi(r[5],r[7]);
    DIF_BF1(r[8],r[10]);  DIF_BFmi(r[9],r[11]);
    DIF_BF1(r[12],r[14]); DIF_BFmi(r[13],r[15]);

    DIF_BF1(r[0],r[1]);  DIF_BF1(r[2],r[3]);   DIF_BF1(r[4],r[5]);   DIF_BF1(r[6],r[7]);
    DIF_BF1(r[8],r[9]);  DIF_BF1(r[10],r[11]); DIF_BF1(r[12],r[13]); DIF_BF1(r[14],r[15]);
}

__device__ __forceinline__ void fft16_dit(float2* r) {
    DIT_BF1(r[0],r[1]);  DIT_BF1(r[2],r[3]);   DIT_BF1(r[4],r[5]);   DIT_BF1(r[6],r[7]);
    DIT_BF1(r[8],r[9]);  DIT_BF1(r[10],r[11]); DIT_BF1(r[12],r[13]); DIT_BF1(r[14],r[15]);

    DIT_BF1(r[0],r[2]);   DIT_BFpi(r[1],r[3]);
    DIT_BF1(r[4],r[6]);   DIT_BFpi(r[5],r[7]);
    DIT_BF1(r[8],r[10]);  DIT_BFpi(r[9],r[11]);
    DIT_BF1(r[12],r[14]); DIT_BFpi(r[13],r[15]);

    DIT_BF1(r[0],r[4]);  DIT_BF(r[1],r[5],R2f,R2f);   DIT_BFpi(r[2],r[6]);   DIT_BF(r[3],r[7],-R2f,R2f);
    DIT_BF1(r[8],r[12]); DIT_BF(r[9],r[13],R2f,R2f);  DIT_BFpi(r[10],r[14]); DIT_BF(r[11],r[15],-R2f,R2f);

    DIT_BF1(r[0],r[8]);
    DIT_BF (r[1],r[9],  C1f,S1f);
    DIT_BF (r[2],r[10], R2f,R2f);
    DIT_BF (r[3],r[11], S1f,C1f);
    DIT_BFpi(r[4],r[12]);
    DIT_BF (r[5],r[13],-S1f,C1f);
    DIT_BF (r[6],r[14],-R2f,R2f);
    DIT_BF (r[7],r[15],-C1f,S1f);
}

// ---------------- 5 register stages on the stride-16 residue class ----------------
// Thread owns indices i = q + 16*m, m = 0..31. Forward DIF stages len = 256..16.
__device__ __forceinline__ void stages5_fwd(float2* v, int q, const float2* tw) {
#pragma unroll
    for (int s = 0; s < 5; s++) {
        const int lp = 16 >> s;
#pragma unroll
        for (int base = 0; base < 32; base += 2 * lp) {
#pragma unroll
            for (int jm = 0; jm < lp; jm++) {
                int m0 = base + jm, m1 = m0 + lp;
                float2 w = tw[(q + 16 * jm) << s];
                float2 a = v[m0], b = v[m1];
                v[m0] = cadd(a, b);
                v[m1] = cmul(csub(a, b), w);
            }
        }
    }
}
// Inverse DIT stages len = 16..256.
__device__ __forceinline__ void stages5_inv(float2* v, int q, const float2* tw) {
#pragma unroll
    for (int e = 0; e < 5; e++) {
        const int lp = 1 << e;
        const int mult = 16 >> e;
#pragma unroll
        for (int base = 0; base < 32; base += 2 * lp) {
#pragma unroll
            for (int jm = 0; jm < lp; jm++) {
                int m0 = base + jm, m1 = m0 + lp;
                float2 w = tw[(q + 16 * jm) * mult];
                float2 cc = cmulc(v[m1], w);
                float2 a = v[m0];
                v[m0] = cadd(a, cc);
                v[m1] = csub(a, cc);
            }
        }
    }
}

// ---------------- setup kernels ----------------
__global__ void k_init() {
    int t = blockIdx.x * blockDim.x + threadIdx.x;
    if (t < S / 2) {
        float sp, cp;
        sincospif((float)t / (float)(S / 2), &sp, &cp);
        d_tw[t] = make_float2(cp, -sp);
    }
    for (int i = t; i < S * S; i += gridDim.x * blockDim.x)
        d_winner[i] = -1;
}

__global__ void k_scatter(const int* __restrict__ idxx, const int* __restrict__ idxy) {
    int p = blockIdx.x * blockDim.x + threadIdx.x;
    if (p >= PNUM) return;
    int u = (idxx[p] + S / 2) & (S - 1);
    int v = (idxy[p] + S / 2) & (S - 1);
    atomicMax(&d_winner[brev9(u) * S + brev9(v)], p);
}

// Build permuted (own, partner) cid table: pos = rs*512 + half*256 + j*16 + q  <->  cell (rs, i=half*256+16q+j)
__global__ void k_cidp(const int* __restrict__ cluster_id) {
    int tid = blockIdx.x * blockDim.x + threadIdx.x;
    if (tid >= S * S) return;
    int rs = tid >> 9, rem = tid & 511;
    int half = rem >> 8, j = (rem >> 4) & 15, q = rem & 15;
    int i = half * 256 + 16 * q + j;
    int kt = brev9((S - brev9(i)) & (S - 1));
    int pr = brev9((S - brev9(rs)) & (S - 1));
    int w0 = d_winner[rs * S + i];
    int w1 = d_winner[pr * S + kt];
    int2 cc;
    cc.x = (w0 >= 0) ? cluster_id[w0] : -1;
    cc.y = (w1 >= 0) ? cluster_id[w1] : -1;
    d_cidp[tid] = cc;
}

// ---------------- pass 1: forward FFT along columns, pair-packed ----------------
// grid (32, NPAIR), 256 threads (c = t&15 column, q = t>>4). smem: 8192 float2 + 256 tw.
__global__ void __launch_bounds__(256, 2) k_cols_fwd(const float* __restrict__ x) {
    extern __shared__ float2 sm[];
    float2* smtw = sm + 8192;
    int t = threadIdx.x;
    smtw[t] = d_tw[t];
    int pair = blockIdx.y, k0 = blockIdx.x * 16;
    int c = t & 15, q = t >> 4;

    const float* x0 = x + (size_t)(2 * pair) * S * S + k0 + c;
    const float* x1 = x0 + (size_t)S * S;
    float2 v[32];
#pragma unroll
    for (int m = 0; m < 32; m++) {
        int i = q + 16 * m;
        v[m] = make_float2(x0[(size_t)i * S], x1[(size_t)i * S]);
    }
    __syncthreads();                      // tw ready

    stages5_fwd(v, q, smtw);

#pragma unroll
    for (int m = 0; m < 32; m++) sm[(q + 16 * m) * 16 + c] = v[m];
    __syncthreads();

    float2 r0[16], r1[16];
#pragma unroll
    for (int j = 0; j < 16; j++) {
        r0[j] = sm[(16 * q + j) * 16 + c];
        r1[j] = sm[(256 + 16 * q + j) * 16 + c];
    }
    fft16_dif(r0);
    fft16_dif(r1);

    float2* spp = d_spec + (size_t)pair * S * S + k0 + c;
#pragma unroll
    for (int j = 0; j < 16; j++) {
        spp[(size_t)(16 * q + j) * S]       = r0[j];
        spp[(size_t)(256 + 16 * q + j) * S] = r1[j];
    }
}

// ---------------- pass 2: rows fwd FFT + Hermitian mask combine + inverse ----------------
// grid (32, NPAIR), 256 threads: r = t>>4 row slot (8 conjugate pairs), q = t&15.
// smem: 16 rows * 544 (f-padded) float2 + 256 tw + 128 pi.
#define F_(i) ((i) + ((i) >> 4))
__global__ void __launch_bounds__(256, 2) k_rows_fmi(const float* __restrict__ pi) {
    extern __shared__ float2 sm[];
    float2* smz  = sm;                 // 16*544
    float2* smtw = sm + 16 * 544;      // 256
    float*  spi  = (float*)(smtw + 256);

    int t = threadIdx.x;
    int pair = blockIdx.y;
    int r = t >> 4, q = t & 15;
    smtw[t] = d_tw[t];
    if (t < 2 * NCLUST) spi[t] = pi[(size_t)(2 * pair) * NCLUST + t];

    int bu = blockIdx.x * 8 + (r >> 1);
    int side = r & 1;
    int rs, pslot;
    if (bu == 0) { rs = side; pslot = r; }
    else         { rs = side ? brev9(S - bu) : brev9(bu); pslot = r ^ 1; }

    float2* row = d_spec + ((size_t)pair * S + rs) * S;
    float2* smr = smz + r * 544;
    float2* smp = smz + pslot * 544;

    float2 v[32];
#pragma unroll
    for (int m = 0; m < 32; m++) v[m] = row[q + 16 * m];
    __syncthreads();                        // tw/pi ready

    stages5_fwd(v, q, smtw);

#pragma unroll
    for (int m = 0; m < 32; m++) smr[q + 17 * m] = v[m];   // F_(q+16m) = q+17m
    __syncthreads();

    float2 r0[16], r1[16];
#pragma unroll
    for (int j = 0; j < 16; j++) {
        r0[j] = smr[17 * q + j];            // F_(16q+j)
        r1[j] = smr[272 + 17 * q + j];      // F_(256+16q+j)
    }
    fft16_dif(r0);
    fft16_dif(r1);

    // publish Z for partner reads
#pragma unroll
    for (int j = 0; j < 16; j++) {
        smr[17 * q + j]       = r0[j];
        smr[272 + 17 * q + j] = r1[j];
    }
    __syncthreads();

    // Hermitian mask combine: Y(k) = alpha*Z(k) + beta*conj(Zpartner(kt))
    {
        const float invq = 0.25f / (float)(S * S);
        const int2* cp = d_cidp + rs * S;
#pragma unroll
        for (int j = 0; j < 16; j++) {
            int i = 16 * q + j;
            int2 cc = cp[j * 16 + q];
            float m00 = (cc.x >= 0) ? spi[cc.x] : 1.f;
            float m10 = (cc.x >= 0) ? spi[NCLUST + cc.x] : 1.f;
            float m01 = (cc.y >= 0) ? spi[cc.y] : 1.f;
            float m11 = (cc.y >= 0) ? spi[NCLUST + cc.y] : 1.f;
            float alpha = (m00 + m01 + m10 + m11) * invq;
            float beta  = (m00 + m01 - m10 - m11) * invq;
            int kt = brev9((S - brev9(i)) & (S - 1));
            float2 zp = smp[F_(kt)];
            float2 z = r0[j];
            r0[j] = make_float2(alpha * z.x + beta * zp.x, alpha * z.y - beta * zp.y);
        }
#pragma unroll
        for (int j = 0; j < 16; j++) {
            int i = 256 + 16 * q + j;
            int2 cc = cp[256 + j * 16 + q];
            float m00 = (cc.x >= 0) ? spi[cc.x] : 1.f;
            float m10 = (cc.x >= 0) ? spi[NCLUST + cc.x] : 1.f;
            float m01 = (cc.y >= 0) ? spi[cc.y] : 1.f;
            float m11 = (cc.y >= 0) ? spi[NCLUST + cc.y] : 1.f;
            float alpha = (m00 + m01 + m10 + m11) * invq;
            float beta  = (m00 + m01 - m10 - m11) * invq;
            int kt = brev9((S - brev9(i)) & (S - 1));
            float2 zp = smp[F_(kt)];
            float2 z = r1[j];
            r1[j] = make_float2(alpha * z.x + beta * zp.x, alpha * z.y - beta * zp.y);
        }
    }

    fft16_dit(r0);
    fft16_dit(r1);
    __syncthreads();                        // all partner reads done

#pragma unroll
    for (int j = 0; j < 16; j++) {
        smr[17 * q + j]       = r0[j];
        smr[272 + 17 * q + j] = r1[j];
    }
    __syncthreads();

#pragma unroll
    for (int m = 0; m < 32; m++) v[m] = smr[q + 17 * m];

    stages5_inv(v, q, smtw);

#pragma unroll
    for (int m = 0; m < 32; m++) row[q + 16 * m] = v[m];
}

// ---------------- pass 3: inverse FFT along columns, unpack to two real planes ----------------
__global__ void __launch_bounds__(256, 2) k_cols_inv(float* __restrict__ out) {
    extern __shared__ float2 sm[];
    float2* smtw = sm + 8192;
    int t = threadIdx.x;
    smtw[t] = d_tw[t];
    int pair = blockIdx.y, k0 = blockIdx.x * 16;
    int c = t & 15, q = t >> 4;

    float2* spp = d_spec + (size_t)pair * S * S + k0 + c;
    float2 r0[16], r1[16];
#pragma unroll
    for (int j = 0; j < 16; j++) {
        r0[j] = spp[(size_t)(16 * q + j) * S];
        r1[j] = spp[(size_t)(256 + 16 * q + j) * S];
    }
    fft16_dit(r0);
    fft16_dit(r1);

#pragma unroll
    for (int j = 0; j < 16; j++) {
        sm[(16 * q + j) * 16 + c]       = r0[j];
        sm[(256 + 16 * q + j) * 16 + c] = r1[j];
    }
    __syncthreads();                        // also covers tw

    float2 v[32];
#pragma unroll
    for (int m = 0; m < 32; m++) v[m] = sm[(q + 16 * m) * 16 + c];

    stages5_inv(v, q, smtw);

    float* o0 = out + (size_t)(2 * pair) * S * S + k0 + c;
    float* o1 = o0 + (size_t)S * S;
#pragma unroll
    for (int m = 0; m < 32; m++) {
        int i = q + 16 * m;
        o0[(size_t)i * S] = v[m].x;
        o1[(size_t)i * S] = v[m].y;
    }
}

// ---------------- launch ----------------
extern "C" void kernel_launch(void* const* d_in, const int* in_sizes, int n_in,
                              void* d_out, int out_size) {
    const float* x    = (const float*)d_in[0];
    const float* pi   = (const float*)d_in[1];
    const int*   idxx = (const int*)d_in[2];
    const int*   idxy = (const int*)d_in[3];
    const int*   cid  = (const int*)d_in[4];
    float* out = (float*)d_out;

    const int smemCols = (8192 + 256) * sizeof(float2);                 // 67584
    const int smemRows = (16 * 544 + 256) * sizeof(float2) + 128 * 4;   // 72192
    cudaFuncSetAttribute(k_cols_fwd, cudaFuncAttributeMaxDynamicSharedMemorySize, smemCols);
    cudaFuncSetAttribute(k_cols_inv, cudaFuncAttributeMaxDynamicSharedMemorySize, smemCols);
    cudaFuncSetAttribute(k_rows_fmi, cudaFuncAttributeMaxDynamicSharedMemorySize, smemRows);

    k_init<<<256, 1024>>>();
    k_scatter<<<PNUM / 256, 256>>>(idxx, idxy);
    k_cidp<<<PNUM / 256, 256>>>(cid);

    dim3 g(32, NPAIR);
    k_cols_fwd<<<g, 256, smemCols>>>(x);
    k_rows_fmi<<<g, 256, smemRows>>>(pi);
    k_cols_inv<<<g, 256, smemCols>>>(out);
}